// round 15
// baseline (speedup 1.0000x reference)
#include <cuda_runtime.h>
#include <cuda_fp16.h>

// R15: 1 point/thread (min MLP_p1 -> min cross-CTA L1tex-queue spread),
// fp16 quad table, vectorized build.
//   d_in[0] = points [N,2] fp32, d_in[1] = grid [1024,1024] fp32,
//   d_in[2] = bounds [2,2] fp32, d_out = [N] fp32

#define GRID_W 1024
#define GRID_H 1024
#define QUAD_STRIDE 1024
#define QUAD_ROWS   (GRID_H - 1)

// quad[y*1024 + x] = half2(tl,tr), half2(bl,br) -> uint2, 8.4 MB
__device__ uint2 g_quad[QUAD_ROWS * QUAD_STRIDE];

__global__ __launch_bounds__(256)
void build_quad_kernel(const float* __restrict__ grid) {
    int t = blockIdx.x * blockDim.x + threadIdx.x;     // [0, 1023*256)
    if (t >= QUAD_ROWS * (GRID_W / 4)) return;
    int y  = t >> 8;            // row 0..1022
    int xb = (t & 255) << 2;    // x block start: 0,4,...,1020

    const float* r0 = grid + (y << 10) + xb;
    const float* r1 = r0 + GRID_W;

    float4 a0 = *reinterpret_cast<const float4*>(r0);
    float4 a1 = *reinterpret_cast<const float4*>(r1);
    int noff = (xb == GRID_W - 4) ? 3 : 4;   // quad at x=1023 never gathered
    float e0 = r0[noff];
    float e1 = r1[noff];

    float t0[5] = {a0.x, a0.y, a0.z, a0.w, e0};
    float b0[5] = {a1.x, a1.y, a1.z, a1.w, e1};

    uint2 q[4];
#pragma unroll
    for (int k = 0; k < 4; k++) {
        __half2 top = __floats2half2_rn(t0[k], t0[k + 1]);
        __half2 bot = __floats2half2_rn(b0[k], b0[k + 1]);
        q[k].x = *reinterpret_cast<unsigned int*>(&top);
        q[k].y = *reinterpret_cast<unsigned int*>(&bot);
    }

    uint2* dst = &g_quad[(y << 10) + xb];
    reinterpret_cast<uint4*>(dst)[0] = make_uint4(q[0].x, q[0].y, q[1].x, q[1].y);
    reinterpret_cast<uint4*>(dst)[1] = make_uint4(q[2].x, q[2].y, q[3].x, q[3].y);
}

// 1 point per thread: minimal front-batched LDG count (MLP_p1 = 1),
// latency hidden by warp count (64 warps/SM).
__global__ __launch_bounds__(256, 8)
void tableInterp_kernel(const float2* __restrict__ pts,
                        const float* __restrict__ bounds,
                        float* __restrict__ out,
                        int n_pts) {
    int i = blockIdx.x * blockDim.x + threadIdx.x;
    if (i >= n_pts) return;

    float x_lo = __ldg(bounds + 0);
    float x_hi = __ldg(bounds + 1);
    float v_lo = __ldg(bounds + 2);
    float v_hi = __ldg(bounds + 3);
    float sy = (float)(GRID_H - 1) / (x_hi - x_lo);
    float sx = (float)(GRID_W - 1) / (v_hi - v_lo);

    float2 p = __ldcs(&pts[i]);   // coalesced 8B/lane

    float qy = (p.x - x_lo) * sy;
    float qx = (p.y - v_lo) * sx;
    float fy = fminf(fmaxf(floorf(qy), 0.0f), (float)(GRID_H - 2));
    float fx = fminf(fmaxf(floorf(qx), 0.0f), (float)(GRID_W - 2));
    float ay = fminf(fmaxf(qy - fy, 0.0f), 1.0f);
    float ax = fminf(fmaxf(qx - fx, 0.0f), 1.0f);
    int idx = (((int)fy) << 10) + (int)fx;

    uint2 q = __ldg(&g_quad[idx]);   // single divergent gather

    float2 t = __half22float2(*reinterpret_cast<const __half2*>(&q.x)); // tl, tr
    float2 b = __half22float2(*reinterpret_cast<const __half2*>(&q.y)); // bl, br
    float top = fmaf(t.y - t.x, ax, t.x);
    float bot = fmaf(b.y - b.x, ax, b.x);
    float r = fmaf(bot - top, ay, top);

    __stcs(out + i, r);   // coalesced 4B/lane
}

extern "C" void kernel_launch(void* const* d_in, const int* in_sizes, int n_in,
                              void* d_out, int out_size) {
    const float2* pts  = (const float2*)d_in[0];
    const float*  grid = (const float*)d_in[1];
    const float*  bnds = (const float*)d_in[2];
    float*        out  = (float*)d_out;

    {
        int total = QUAD_ROWS * (GRID_W / 4);   // 1023 * 256
        int threads = 256;
        int blocks = (total + threads - 1) / threads;
        build_quad_kernel<<<blocks, threads>>>(grid);
    }

    int n = in_sizes[0] / 2;   // number of points ([N,2]) = 4,194,304

    int threads = 256;
    int blocks = (n + threads - 1) / threads;   // 16384
    tableInterp_kernel<<<blocks, threads>>>(pts, bnds, out, n);
}

// round 16
// speedup vs baseline: 1.0655x; 1.0655x over previous
#include <cuda_runtime.h>
#include <cuda_fp16.h>

// R16 = R14 champion + __ldcg (L2-cached, L1-bypass) on the quad gathers.
// Tests whether useless L1 sector fills (~2.7% hit rate on an 8.4MB table)
// are part of the 1.5 cyc/point random-gather wall.
//   d_in[0] = points [N,2] fp32, d_in[1] = grid [1024,1024] fp32,
//   d_in[2] = bounds [2,2] fp32, d_out = [N] fp32

#define GRID_W 1024
#define GRID_H 1024
#define QUAD_STRIDE 1024
#define QUAD_ROWS   (GRID_H - 1)

// quad[y*1024 + x] = half2(tl,tr), half2(bl,br) -> uint2, 8.4 MB
__device__ uint2 g_quad[QUAD_ROWS * QUAD_STRIDE];

// Build: each thread produces 4 consecutive quads of one row (2 x 16B stores).
__global__ __launch_bounds__(256)
void build_quad_kernel(const float* __restrict__ grid) {
    int t = blockIdx.x * blockDim.x + threadIdx.x;     // [0, 1023*256)
    if (t >= QUAD_ROWS * (GRID_W / 4)) return;
    int y  = t >> 8;            // row 0..1022
    int xb = (t & 255) << 2;    // x block start: 0,4,...,1020

    const float* r0 = grid + (y << 10) + xb;
    const float* r1 = r0 + GRID_W;

    float4 a0 = *reinterpret_cast<const float4*>(r0);
    float4 a1 = *reinterpret_cast<const float4*>(r1);
    int noff = (xb == GRID_W - 4) ? 3 : 4;   // quad at x=1023 never gathered
    float e0 = r0[noff];
    float e1 = r1[noff];

    float t0[5] = {a0.x, a0.y, a0.z, a0.w, e0};
    float b0[5] = {a1.x, a1.y, a1.z, a1.w, e1};

    uint2 q[4];
#pragma unroll
    for (int k = 0; k < 4; k++) {
        __half2 top = __floats2half2_rn(t0[k], t0[k + 1]);
        __half2 bot = __floats2half2_rn(b0[k], b0[k + 1]);
        q[k].x = *reinterpret_cast<unsigned int*>(&top);
        q[k].y = *reinterpret_cast<unsigned int*>(&bot);
    }

    uint2* dst = &g_quad[(y << 10) + xb];
    reinterpret_cast<uint4*>(dst)[0] = make_uint4(q[0].x, q[0].y, q[1].x, q[1].y);
    reinterpret_cast<uint4*>(dst)[1] = make_uint4(q[2].x, q[2].y, q[3].x, q[3].y);
}

__global__ __launch_bounds__(128, 16)
void tableInterp_kernel(const float4* __restrict__ pts,
                        const float* __restrict__ bounds,
                        float* __restrict__ out,
                        int n_quads) {   // groups of 4 points
    int i = blockIdx.x * blockDim.x + threadIdx.x;
    if (i >= n_quads) return;

    float x_lo = __ldg(bounds + 0);
    float x_hi = __ldg(bounds + 1);
    float v_lo = __ldg(bounds + 2);
    float v_hi = __ldg(bounds + 3);
    float sy = (float)(GRID_H - 1) / (x_hi - x_lo);
    float sx = (float)(GRID_W - 1) / (v_hi - v_lo);

    // Streaming, read-once point data.
    float4 p01 = __ldcs(&pts[2 * i]);
    float4 p23 = __ldcs(&pts[2 * i + 1]);

    float px[4] = {p01.x, p01.z, p23.x, p23.z};
    float pv[4] = {p01.y, p01.w, p23.y, p23.w};

    // Phase 1: indices + alphas (pure ALU).
    int   idx[4];
    float ax[4], ay[4];
#pragma unroll
    for (int k = 0; k < 4; k++) {
        float qy = (px[k] - x_lo) * sy;
        float qx = (pv[k] - v_lo) * sx;
        float fy = fminf(fmaxf(floorf(qy), 0.0f), (float)(GRID_H - 2));
        float fx = fminf(fmaxf(floorf(qx), 0.0f), (float)(GRID_W - 2));
        ay[k] = fminf(fmaxf(qy - fy, 0.0f), 1.0f);
        ax[k] = fminf(fmaxf(qx - fx, 0.0f), 1.0f);
        idx[k] = (((int)fy) << 10) + (int)fx;
    }

    // Phase 2: 4 independent gathers, L2-cached / L1-bypass (ld.global.cg).
    uint2 q[4];
#pragma unroll
    for (int k = 0; k < 4; k++) q[k] = __ldcg(&g_quad[idx[k]]);

    // Phase 3: convert + blend + streaming store.
    float r[4];
#pragma unroll
    for (int k = 0; k < 4; k++) {
        float2 t = __half22float2(*reinterpret_cast<const __half2*>(&q[k].x)); // tl, tr
        float2 b = __half22float2(*reinterpret_cast<const __half2*>(&q[k].y)); // bl, br
        float top = fmaf(t.y - t.x, ax[k], t.x);
        float bot = fmaf(b.y - b.x, ax[k], b.x);
        r[k] = fmaf(bot - top, ay[k], top);
    }

    __stcs(reinterpret_cast<float4*>(out) + i, make_float4(r[0], r[1], r[2], r[3]));
}

extern "C" void kernel_launch(void* const* d_in, const int* in_sizes, int n_in,
                              void* d_out, int out_size) {
    const float4* pts  = (const float4*)d_in[0];
    const float*  grid = (const float*)d_in[1];
    const float*  bnds = (const float*)d_in[2];
    float*        out  = (float*)d_out;

    {
        int total = QUAD_ROWS * (GRID_W / 4);   // 1023 * 256
        int threads = 256;
        int blocks = (total + threads - 1) / threads;
        build_quad_kernel<<<blocks, threads>>>(grid);
    }

    int n = in_sizes[0] / 2;   // number of points ([N,2])
    int n_quads = n / 4;       // groups of 4 points

    int threads = 128;
    int blocks = (n_quads + threads - 1) / threads;   // 8192
    tableInterp_kernel<<<blocks, threads>>>(pts, bnds, out, n_quads);
}